// round 1
// baseline (speedup 1.0000x reference)
#include <cuda_runtime.h>
#include <math_constants.h>
#include <math.h>

#define B_      8
#define C_      32
#define K_      5
#define HW_     65536
#define TILES_  32
#define TPX_    2048
#define SST_    1232
#define EPS_    1e-6f
#define CLOG2PI_ (32.0f * 1.8378770664093453f)

// ---- scratch (static device globals; no allocation) ----
__device__ float g_part1[B_ * TILES_ * SST_];
__device__ float g_stats[B_ * SST_];
__device__ float g_P[B_ * K_ * C_ * C_];     // packed upper-tri P, diag halved, lower zero
__device__ float g_Hb[B_ * K_ * C_];         // -q = -(P mu)
__device__ float g_Ck[B_ * K_];              // phi - 0.5*(c*log2pi + logdet + r)
__device__ float g_part2[B_ * K_ * TILES_ * 2];

// =====================================================================
// Kernel 1: per-(b,tile) partial sufficient statistics.
// ZZ (full 32x32), S (32), GZ (5x32), Gs (5) over a 2048-pixel tile.
// =====================================================================
__global__ __launch_bounds__(256) void k_stats(const float* __restrict__ z,
                                               const float* __restrict__ g)
{
    const int tile = blockIdx.x, b = blockIdx.y;
    const int tid = threadIdx.x, w = tid >> 5, l = tid & 31;
    __shared__ float zs[32][257];   // pad 1 -> conflict-free column access
    __shared__ float gs[5][257];
    const float* zb = z + (size_t)b * C_ * HW_;
    const float* gb = g + (size_t)b * K_ * HW_;
    const int base0 = tile * TPX_;

    float a0 = 0.f, a1 = 0.f, a2 = 0.f, a3 = 0.f, ag = 0.f, as = 0.f, ags = 0.f;
    const int c0 = w, c1 = w + 8, c2 = w + 16, c3 = w + 24;

    for (int ch = 0; ch < 8; ++ch) {
        const int base = base0 + (ch << 8);
        __syncthreads();
        #pragma unroll
        for (int r = 0; r < 32; ++r)        // tid is the pixel index within chunk
            zs[r][tid] = zb[r * HW_ + base + tid];
        #pragma unroll
        for (int r = 0; r < 5; ++r)
            gs[r][tid] = gb[r * HW_ + base + tid];
        __syncthreads();

        #pragma unroll 4
        for (int x = 0; x < 256; ++x) {
            float v = zs[l][x];             // lane-indexed: conflict-free
            a0 = fmaf(zs[c0][x], v, a0);    // row values: broadcast
            a1 = fmaf(zs[c1][x], v, a1);
            a2 = fmaf(zs[c2][x], v, a2);
            a3 = fmaf(zs[c3][x], v, a3);
            if (w < 5)           ag  = fmaf(gs[w][x], v, ag);
            if (w == 5)          as += v;
            if (w == 6 && l < 5) ags += gs[l][x];
        }
    }

    float* p = g_part1 + (size_t)(b * TILES_ + tile) * SST_;
    p[c0 * 32 + l] = a0;
    p[c1 * 32 + l] = a1;
    p[c2 * 32 + l] = a2;
    p[c3 * 32 + l] = a3;
    if (w < 5)           p[1024 + w * 32 + l] = ag;
    if (w == 5)          p[1184 + l] = as;
    if (w == 6 && l < 5) p[1216 + l] = ags;
}

// =====================================================================
// Kernel 2a: deterministic tile reduction -> per-b stats
// =====================================================================
__global__ void k_reduce()
{
    const int b = blockIdx.x;
    for (int s = threadIdx.x; s < 1221; s += blockDim.x) {
        float acc = 0.f;
        for (int t = 0; t < TILES_; ++t)
            acc += g_part1[(size_t)(b * TILES_ + t) * SST_ + s];
        g_stats[b * SST_ + s] = acc;
    }
}

__device__ __forceinline__ float wsum(float v)
{
    #pragma unroll
    for (int o = 16; o; o >>= 1) v += __shfl_xor_sync(0xffffffffu, v, o);
    return v;
}

// =====================================================================
// Kernel 2b: per-(b,k) mu, cov, Cholesky, P = L^-T L^-1, q, r, logdet.
// One warp per (b,k). 40 blocks of 32 threads.
// =====================================================================
__global__ __launch_bounds__(32) void k_prep()
{
    const int bk = blockIdx.x;
    const int b = bk / K_, k = bk % K_;
    const int l = threadIdx.x;
    __shared__ float A [32][33];
    __shared__ float Ai[32][33];
    __shared__ float Pm[32][33];
    __shared__ float mu[32], Sv[32];

    const float* st = g_stats + b * SST_;
    const float Gs = st[1216 + k];

    // mu = GZ/(Gs+eps), then L2-normalize over channels
    float m = st[1024 + k * 32 + l] / (Gs + EPS_);
    float nrm = sqrtf(wsum(m * m));
    m = m / (EPS_ + nrm);
    mu[l] = m; Sv[l] = st[1184 + l];
    __syncwarp();

    // cov = ZZ - mu S^T - S mu^T + hw mu mu^T
    #pragma unroll 1
    for (int i = 0; i < 32; ++i)
        A[i][l] = st[i * 32 + l] - mu[i] * Sv[l] - m * Sv[i] + 65536.0f * mu[i] * m;
    __syncwarp();

    // diag += max(diag, eps)
    {
        float dg = A[l][l];
        A[l][l] = dg + fmaxf(dg, EPS_);
    }
    __syncwarp();

    // Frobenius normalize
    float sq = 0.f;
    for (int i = 0; i < 32; ++i) sq += A[i][l] * A[i][l];
    float fro = sqrtf(wsum(sq));
    float sc = 1.0f / (EPS_ + fro);
    for (int i = 0; i < 32; ++i) A[i][l] *= sc;
    __syncwarp();

    // Cholesky (lower, in place)
    for (int j = 0; j < 32; ++j) {
        if (l == 0) A[j][j] = sqrtf(A[j][j]);
        __syncwarp();
        float inv = 1.0f / A[j][j];
        if (l > j) A[l][j] *= inv;
        __syncwarp();
        for (int m2 = j + 1; m2 < 32; ++m2) {
            float lmj = A[m2][j];
            if (l >= m2) A[l][m2] = fmaf(-A[l][j], lmj, A[l][m2]);
        }
        __syncwarp();
    }
    float logdet2 = 2.0f * wsum(logf(A[l][l]));

    // Ai = L^-1 (lower); lane l owns column l
    for (int i = 0; i < 32; ++i) Ai[i][l] = 0.0f;
    __syncwarp();
    Ai[l][l] = 1.0f / A[l][l];
    for (int i = l + 1; i < 32; ++i) {
        float s = 0.f;
        for (int m2 = l; m2 < i; ++m2) s = fmaf(A[i][m2], Ai[m2][l], s);
        Ai[i][l] = -s / A[i][i];
    }
    __syncwarp();

    // P = Ai^T Ai
    for (int i = 0; i < 32; ++i) {
        float s = 0.f;
        for (int m2 = 0; m2 < 32; ++m2) s = fmaf(Ai[m2][i], Ai[m2][l], s);
        Pm[i][l] = s;
    }
    __syncwarp();

    // q = P mu, r = mu^T P mu
    float q = 0.f;
    for (int j = 0; j < 32; ++j) q = fmaf(Pm[l][j], mu[j], q);
    float r = wsum(mu[l] * q);

    // pack: upper triangle, halved diagonal, zero below
    float* Pd = g_P + (size_t)bk * (C_ * C_);
    for (int i = 0; i < 32; ++i) {
        float v = (l < i) ? 0.0f : ((l == i) ? 0.5f * Pm[i][i] : Pm[i][l]);
        Pd[i * 32 + l] = v;
    }
    g_Hb[bk * C_ + l] = -q;
    if (l == 0) {
        float phi = Gs / 65536.0f;
        g_Ck[bk] = phi - 0.5f * (CLOG2PI_ + logdet2 + r);
    }
}

// =====================================================================
// Kernel 3: per-pixel quadratic form + fused online logsumexp.
// Grid (tile*K + k, b): 1280 blocks of 256 threads, 8 pixels/thread.
// v_n = -( z^T P z /2 - q.z )  (r folded into the constant)
// =====================================================================
__global__ __launch_bounds__(256) void k_maha(const float* __restrict__ z)
{
    const int k    = blockIdx.x % K_;
    const int tile = blockIdx.x / K_;
    const int b    = blockIdx.y;
    const int tid  = threadIdx.x;

    __shared__ __align__(16) float Ps[1024];
    __shared__ float Hs[32];
    __shared__ float rm[256], rs[256];

    const float* Pd = g_P + (size_t)(b * K_ + k) * 1024;
    #pragma unroll
    for (int r = 0; r < 4; ++r) Ps[tid + r * 256] = Pd[tid + r * 256];
    if (tid < 32) Hs[tid] = g_Hb[(b * K_ + k) * 32 + tid];
    __syncthreads();

    const float* zb = z + (size_t)b * C_ * HW_;
    const int base = tile * TPX_;

    float mx = -CUDART_INF_F, sm = 0.0f;

    #pragma unroll 1
    for (int p = 0; p < 8; ++p) {
        const int n = base + (p << 8) + tid;
        float zr[32];
        #pragma unroll
        for (int c = 0; c < 32; ++c) zr[c] = zb[c * HW_ + n];

        float s = 0.0f;
        #pragma unroll
        for (int c = 0; c < 32; ++c) {
            float t = Hs[c];
            #pragma unroll
            for (int j = (c & ~3); j < 32; j += 4) {
                float4 pv = *reinterpret_cast<const float4*>(&Ps[c * 32 + j]);
                t = fmaf(pv.x, zr[j + 0], t);
                t = fmaf(pv.y, zr[j + 1], t);
                t = fmaf(pv.z, zr[j + 2], t);
                t = fmaf(pv.w, zr[j + 3], t);
            }
            s = fmaf(zr[c], t, s);
        }
        float v = -s;
        float nm = fmaxf(mx, v);
        sm = fmaf(sm, __expf(mx - nm), __expf(v - nm));
        mx = nm;
    }

    rm[tid] = mx; rs[tid] = sm;
    __syncthreads();
    for (int off = 128; off; off >>= 1) {
        if (tid < off) {
            float m2 = rm[tid + off], s2 = rs[tid + off];
            float nm = fmaxf(rm[tid], m2);
            rs[tid] = rs[tid] * __expf(rm[tid] - nm) + s2 * __expf(m2 - nm);
            rm[tid] = nm;
        }
        __syncthreads();
    }
    if (tid == 0) {
        float* o = g_part2 + (size_t)((b * K_ + k) * TILES_ + tile) * 2;
        o[0] = rm[0]; o[1] = rs[0];
    }
}

// =====================================================================
// Kernel 4: combine tile partials -> energy scalar
// =====================================================================
__global__ void k_final(float* __restrict__ out)
{
    __shared__ float acc[64];
    const int t = threadIdx.x;
    float val = 0.0f;
    if (t < B_ * K_) {
        float m = -CUDART_INF_F, s = 0.0f;
        for (int tile = 0; tile < TILES_; ++tile) {
            const float* o = g_part2 + (size_t)(t * TILES_ + tile) * 2;
            float m2 = o[0], s2 = o[1];
            float nm = fmaxf(m, m2);
            s = s * __expf(m - nm) + s2 * __expf(m2 - nm);
            m = nm;
        }
        val = g_Ck[t] + m + logf(s);
    }
    acc[t] = val;
    __syncthreads();
    for (int off = 32; off; off >>= 1) {
        if (t < off) acc[t] += acc[t + off];
        __syncthreads();
    }
    if (t == 0) out[0] = -(acc[0] / 40.0f) / 65536.0f;
}

// =====================================================================
extern "C" void kernel_launch(void* const* d_in, const int* in_sizes, int n_in,
                              void* d_out, int out_size)
{
    (void)in_sizes; (void)n_in; (void)out_size;
    const float* z = (const float*)d_in[0];
    const float* g = (const float*)d_in[1];

    k_stats <<<dim3(TILES_, B_), 256>>>(z, g);
    k_reduce<<<B_, 256>>>();
    k_prep  <<<B_ * K_, 32>>>();
    k_maha  <<<dim3(TILES_ * K_, B_), 256>>>(z);
    k_final <<<1, 64>>>((float*)d_out);
}

// round 3
// speedup vs baseline: 3.5454x; 3.5454x over previous
#include <cuda_runtime.h>
#include <math_constants.h>
#include <math.h>

#define B_      8
#define C_      32
#define K_      5
#define HW_     65536
#define TILES_  32
#define TPX_    2048
#define SST_    1232
#define CHUNKS_ 64
#define EPS_    1e-6f
#define CLOG2PI_ (32.0f * 1.8378770664093453f)

// ---- scratch (static device globals; no allocation) ----
__device__ float g_part1[B_ * TILES_ * SST_];
__device__ float g_stats[B_ * SST_];
__device__ float g_P[B_ * K_ * C_ * C_];     // packed upper-tri P, diag halved, lower zero
__device__ float g_Hb[B_ * K_ * C_];         // -q = -(P mu)
__device__ float g_Ck[B_ * K_];              // phi - 0.5*(c*log2pi + logdet + r)
__device__ float g_part2[B_ * K_ * CHUNKS_ * 2];

// =====================================================================
// Kernel 1: per-(b,tile) partial sufficient statistics.
// ZZ (full 32x32), S (32), GZ (5x32), Gs (5) over a 2048-pixel tile.
// =====================================================================
__global__ __launch_bounds__(256) void k_stats(const float* __restrict__ z,
                                               const float* __restrict__ g)
{
    const int tile = blockIdx.x, b = blockIdx.y;
    const int tid = threadIdx.x, w = tid >> 5, l = tid & 31;
    __shared__ float zs[32][257];   // pad 1 -> conflict-free column access
    __shared__ float gs[5][257];
    const float* zb = z + (size_t)b * C_ * HW_;
    const float* gb = g + (size_t)b * K_ * HW_;
    const int base0 = tile * TPX_;

    float a0 = 0.f, a1 = 0.f, a2 = 0.f, a3 = 0.f, ag = 0.f, as = 0.f, ags = 0.f;
    const int c0 = w, c1 = w + 8, c2 = w + 16, c3 = w + 24;

    for (int ch = 0; ch < 8; ++ch) {
        const int base = base0 + (ch << 8);
        __syncthreads();
        #pragma unroll
        for (int r = 0; r < 32; ++r)        // tid is the pixel index within chunk
            zs[r][tid] = zb[r * HW_ + base + tid];
        #pragma unroll
        for (int r = 0; r < 5; ++r)
            gs[r][tid] = gb[r * HW_ + base + tid];
        __syncthreads();

        #pragma unroll 4
        for (int x = 0; x < 256; ++x) {
            float v = zs[l][x];             // lane-indexed: conflict-free
            a0 = fmaf(zs[c0][x], v, a0);    // row values: broadcast
            a1 = fmaf(zs[c1][x], v, a1);
            a2 = fmaf(zs[c2][x], v, a2);
            a3 = fmaf(zs[c3][x], v, a3);
            if (w < 5)           ag  = fmaf(gs[w][x], v, ag);
            if (w == 5)          as += v;
            if (w == 6 && l < 5) ags += gs[l][x];
        }
    }

    float* p = g_part1 + (size_t)(b * TILES_ + tile) * SST_;
    p[c0 * 32 + l] = a0;
    p[c1 * 32 + l] = a1;
    p[c2 * 32 + l] = a2;
    p[c3 * 32 + l] = a3;
    if (w < 5)           p[1024 + w * 32 + l] = ag;
    if (w == 5)          p[1184 + l] = as;
    if (w == 6 && l < 5) p[1216 + l] = ags;
}

// =====================================================================
// Kernel 2a: deterministic tile reduction -> per-b stats
// =====================================================================
__global__ void k_reduce()
{
    const int b = blockIdx.x;
    for (int s = threadIdx.x; s < 1221; s += blockDim.x) {
        float acc = 0.f;
        for (int t = 0; t < TILES_; ++t)
            acc += g_part1[(size_t)(b * TILES_ + t) * SST_ + s];
        g_stats[b * SST_ + s] = acc;
    }
}

__device__ __forceinline__ float wsum(float v)
{
    #pragma unroll
    for (int o = 16; o; o >>= 1) v += __shfl_xor_sync(0xffffffffu, v, o);
    return v;
}

// =====================================================================
// Kernel 2b: per-(b,k) mu, cov, Cholesky, P = L^-T L^-1, q, r, logdet.
// One warp per (b,k). 40 blocks of 32 threads.
// =====================================================================
__global__ __launch_bounds__(32) void k_prep()
{
    const int bk = blockIdx.x;
    const int b = bk / K_, k = bk % K_;
    const int l = threadIdx.x;
    __shared__ float A [32][33];
    __shared__ float Ai[32][33];
    __shared__ float Pm[32][33];
    __shared__ float mu[32], Sv[32];

    const float* st = g_stats + b * SST_;
    const float Gs = st[1216 + k];

    // mu = GZ/(Gs+eps), then L2-normalize over channels
    float m = st[1024 + k * 32 + l] / (Gs + EPS_);
    float nrm = sqrtf(wsum(m * m));
    m = m / (EPS_ + nrm);
    mu[l] = m; Sv[l] = st[1184 + l];
    __syncwarp();

    // cov = ZZ - mu S^T - S mu^T + hw mu mu^T
    #pragma unroll 1
    for (int i = 0; i < 32; ++i)
        A[i][l] = st[i * 32 + l] - mu[i] * Sv[l] - m * Sv[i] + 65536.0f * mu[i] * m;
    __syncwarp();

    // diag += max(diag, eps)
    {
        float dg = A[l][l];
        A[l][l] = dg + fmaxf(dg, EPS_);
    }
    __syncwarp();

    // Frobenius normalize
    float sq = 0.f;
    for (int i = 0; i < 32; ++i) sq += A[i][l] * A[i][l];
    float fro = sqrtf(wsum(sq));
    float sc = 1.0f / (EPS_ + fro);
    for (int i = 0; i < 32; ++i) A[i][l] *= sc;
    __syncwarp();

    // Cholesky (lower, in place)
    for (int j = 0; j < 32; ++j) {
        if (l == 0) A[j][j] = sqrtf(A[j][j]);
        __syncwarp();
        float inv = 1.0f / A[j][j];
        if (l > j) A[l][j] *= inv;
        __syncwarp();
        for (int m2 = j + 1; m2 < 32; ++m2) {
            float lmj = A[m2][j];
            if (l >= m2) A[l][m2] = fmaf(-A[l][j], lmj, A[l][m2]);
        }
        __syncwarp();
    }
    float logdet2 = 2.0f * wsum(logf(A[l][l]));

    // Ai = L^-1 (lower); lane l owns column l
    for (int i = 0; i < 32; ++i) Ai[i][l] = 0.0f;
    __syncwarp();
    Ai[l][l] = 1.0f / A[l][l];
    for (int i = l + 1; i < 32; ++i) {
        float s = 0.f;
        for (int m2 = l; m2 < i; ++m2) s = fmaf(A[i][m2], Ai[m2][l], s);
        Ai[i][l] = -s / A[i][i];
    }
    __syncwarp();

    // P = Ai^T Ai
    for (int i = 0; i < 32; ++i) {
        float s = 0.f;
        for (int m2 = 0; m2 < 32; ++m2) s = fmaf(Ai[m2][i], Ai[m2][l], s);
        Pm[i][l] = s;
    }
    __syncwarp();

    // q = P mu, r = mu^T P mu
    float q = 0.f;
    for (int j = 0; j < 32; ++j) q = fmaf(Pm[l][j], mu[j], q);
    float r = wsum(mu[l] * q);

    // pack: upper triangle, halved diagonal, zero below
    float* Pd = g_P + (size_t)bk * (C_ * C_);
    for (int i = 0; i < 32; ++i) {
        float v = (l < i) ? 0.0f : ((l == i) ? 0.5f * Pm[i][i] : Pm[i][l]);
        Pd[i * 32 + l] = v;
    }
    g_Hb[bk * C_ + l] = -q;
    if (l == 0) {
        float phi = Gs / 65536.0f;
        g_Ck[bk] = phi - 0.5f * (CLOG2PI_ + logdet2 + r);
    }
}

// =====================================================================
// Kernel 3: per-pixel quadratic form for ALL 5 components per block
// (z loaded ONCE per pixel, reused 5x), fused online logsumexp.
// Grid (CHUNKS_, B_), 256 threads, 4 pixels per thread.
// v_n = -( z^T P z /2 - q.z )  (r folded into the constant)
// =====================================================================
__global__ __launch_bounds__(256, 3) void k_maha(const float* __restrict__ z)
{
    const int chunk = blockIdx.x;
    const int b     = blockIdx.y;
    const int tid   = threadIdx.x;
    const int wid   = tid >> 5, lid = tid & 31;

    __shared__ __align__(16) float Ps[K_ * 1024];   // 20KB: 5 packed P
    __shared__ float Hs[K_ * 32];
    __shared__ float rmx[8 * K_], rsm[8 * K_];

    const float* Pb = g_P + (size_t)b * K_ * 1024;
    #pragma unroll
    for (int r = 0; r < K_ * 4; ++r) Ps[tid + r * 256] = Pb[tid + r * 256];
    if (tid < K_ * 32) Hs[tid] = g_Hb[b * K_ * 32 + tid];
    __syncthreads();

    const float* zb = z + (size_t)b * C_ * HW_;

    float mxk[K_], smk[K_];
    #pragma unroll
    for (int k = 0; k < K_; ++k) { mxk[k] = -CUDART_INF_F; smk[k] = 0.0f; }

    #pragma unroll 1
    for (int p = 0; p < 4; ++p) {
        const int n = chunk * 1024 + (p << 8) + tid;
        float zr[32];
        #pragma unroll
        for (int c = 0; c < 32; ++c) zr[c] = zb[(size_t)c * HW_ + n];

        #pragma unroll 1
        for (int k = 0; k < K_; ++k) {
            const float* Pk = &Ps[k * 1024];
            const float* Hk = &Hs[k * 32];
            float s = 0.0f;
            #pragma unroll
            for (int c = 0; c < 32; ++c) {
                float t = Hk[c];
                #pragma unroll
                for (int j = (c & ~3); j < 32; j += 4) {
                    float4 pv = *reinterpret_cast<const float4*>(&Pk[c * 32 + j]);
                    t = fmaf(pv.x, zr[j + 0], t);
                    t = fmaf(pv.y, zr[j + 1], t);
                    t = fmaf(pv.z, zr[j + 2], t);
                    t = fmaf(pv.w, zr[j + 3], t);
                }
                s = fmaf(zr[c], t, s);
            }
            float v = -s;
            float nm = fmaxf(mxk[k], v);
            smk[k] = fmaf(smk[k], __expf(mxk[k] - nm), __expf(v - nm));
            mxk[k] = nm;
        }
    }

    // warp reduce (logsumexp-merge), then cross-warp via smem
    #pragma unroll
    for (int k = 0; k < K_; ++k) {
        float m = mxk[k], s = smk[k];
        #pragma unroll
        for (int o = 16; o; o >>= 1) {
            float m2 = __shfl_xor_sync(0xffffffffu, m, o);
            float s2 = __shfl_xor_sync(0xffffffffu, s, o);
            float nm = fmaxf(m, m2);
            s = s * __expf(m - nm) + s2 * __expf(m2 - nm);
            m = nm;
        }
        if (lid == 0) { rmx[wid * K_ + k] = m; rsm[wid * K_ + k] = s; }
    }
    __syncthreads();
    if (tid < K_) {
        float m = rmx[tid], s = rsm[tid];
        #pragma unroll
        for (int w2 = 1; w2 < 8; ++w2) {
            float m2 = rmx[w2 * K_ + tid], s2 = rsm[w2 * K_ + tid];
            float nm = fmaxf(m, m2);
            s = s * __expf(m - nm) + s2 * __expf(m2 - nm);
            m = nm;
        }
        float* o = g_part2 + (size_t)((b * K_ + tid) * CHUNKS_ + chunk) * 2;
        o[0] = m; o[1] = s;
    }
}

// =====================================================================
// Kernel 4: combine chunk partials -> energy scalar
// =====================================================================
__global__ void k_final(float* __restrict__ out)
{
    __shared__ float acc[64];
    const int t = threadIdx.x;
    float val = 0.0f;
    if (t < B_ * K_) {
        float m = -CUDART_INF_F, s = 0.0f;
        for (int c = 0; c < CHUNKS_; ++c) {
            const float* o = g_part2 + (size_t)(t * CHUNKS_ + c) * 2;
            float m2 = o[0], s2 = o[1];
            float nm = fmaxf(m, m2);
            s = s * __expf(m - nm) + s2 * __expf(m2 - nm);
            m = nm;
        }
        val = g_Ck[t] + m + logf(s);
    }
    acc[t] = val;
    __syncthreads();
    for (int off = 32; off; off >>= 1) {
        if (t < off) acc[t] += acc[t + off];
        __syncthreads();
    }
    if (t == 0) out[0] = -(acc[0] / 40.0f) / 65536.0f;
}

// =====================================================================
extern "C" void kernel_launch(void* const* d_in, const int* in_sizes, int n_in,
                              void* d_out, int out_size)
{
    (void)in_sizes; (void)n_in; (void)out_size;
    const float* z = (const float*)d_in[0];
    const float* g = (const float*)d_in[1];

    k_stats <<<dim3(TILES_, B_), 256>>>(z, g);
    k_reduce<<<B_, 256>>>();
    k_prep  <<<B_ * K_, 32>>>();
    k_maha  <<<dim3(CHUNKS_, B_), 256>>>(z);
    k_final <<<1, 64>>>((float*)d_out);
}

// round 4
// speedup vs baseline: 5.4279x; 1.5310x over previous
#include <cuda_runtime.h>
#include <math_constants.h>
#include <math.h>

#define B_      8
#define C_      32
#define K_      5
#define HW_     65536
#define TILES_  32
#define TPX_    2048
#define SST_    (4*1024 + 32*5 + 32 + 5 + 27)   // 4 ZZ team slices + GZ + S + Gs
#define ZZOFF_  0
#define GZOFF_  4096
#define SOFF_   (4096 + 160)
#define GSOFF_  (4096 + 192)
#define CHUNKS_ 128
#define EPS_    1e-6f
#define CLOG2PI_ (32.0f * 1.8378770664093453f)

// ---- scratch (static device globals; no allocation) ----
__device__ float g_part1[B_ * TILES_ * SST_];
__device__ float g_P[B_ * K_ * C_ * C_];     // packed upper-tri P, diag halved, lower zero
__device__ float g_Hb[B_ * K_ * C_];         // -q = -(P mu)
__device__ float g_Ck[B_ * K_];              // phi - 0.5*(c*log2pi + logdet + r)
__device__ float g_part2[B_ * K_ * CHUNKS_ * 2];

// =====================================================================
// Kernel 1: per-(b,tile) partial sufficient statistics.
// Register-tiled SYRK: pixel-major smem tile, each thread owns a 4x4
// tile of ZZ; 4 teams split the 256-px chunk. Then a light pass for
// GZ (5x32), S (32), Gs (5).
// =====================================================================
__global__ __launch_bounds__(256, 2) void k_stats(const float* __restrict__ z,
                                                  const float* __restrict__ g)
{
    const int tile = blockIdx.x, b = blockIdx.y;
    const int tid = threadIdx.x, w = tid >> 5, l = tid & 31;
    __shared__ float zs[256][36];   // pixel-major, 16B-aligned rows
    __shared__ float gs[256][8];

    const float* zb = z + (size_t)b * C_ * HW_;
    const float* gb = g + (size_t)b * K_ * HW_;
    const int base0 = tile * TPX_;

    const int team = tid >> 6;          // x-subrange [64*team, 64*team+64)
    const int thr  = tid & 63;
    const int ti   = thr >> 3, tj = thr & 7;   // 4x4 tile at rows 4ti, cols 4tj

    float acc[4][4];
    #pragma unroll
    for (int u = 0; u < 4; ++u)
        #pragma unroll
        for (int v = 0; v < 4; ++v) acc[u][v] = 0.f;
    float accg = 0.f, accs = 0.f, accgs = 0.f;

    #pragma unroll 1
    for (int ch = 0; ch < 8; ++ch) {
        const int base = base0 + (ch << 8);
        __syncthreads();
        #pragma unroll
        for (int c = 0; c < 32; ++c)
            zs[tid][c] = zb[(size_t)c * HW_ + base + tid];
        #pragma unroll
        for (int r = 0; r < 5; ++r)
            gs[tid][r] = gb[(size_t)r * HW_ + base + tid];
        __syncthreads();

        // phase A: SYRK over this team's 64 pixels
        const int x0 = team << 6;
        #pragma unroll 2
        for (int x = x0; x < x0 + 64; ++x) {
            const float4 a  = *reinterpret_cast<const float4*>(&zs[x][4 * ti]);
            const float4 bb = *reinterpret_cast<const float4*>(&zs[x][4 * tj]);
            acc[0][0] = fmaf(a.x, bb.x, acc[0][0]);
            acc[0][1] = fmaf(a.x, bb.y, acc[0][1]);
            acc[0][2] = fmaf(a.x, bb.z, acc[0][2]);
            acc[0][3] = fmaf(a.x, bb.w, acc[0][3]);
            acc[1][0] = fmaf(a.y, bb.x, acc[1][0]);
            acc[1][1] = fmaf(a.y, bb.y, acc[1][1]);
            acc[1][2] = fmaf(a.y, bb.z, acc[1][2]);
            acc[1][3] = fmaf(a.y, bb.w, acc[1][3]);
            acc[2][0] = fmaf(a.z, bb.x, acc[2][0]);
            acc[2][1] = fmaf(a.z, bb.y, acc[2][1]);
            acc[2][2] = fmaf(a.z, bb.z, acc[2][2]);
            acc[2][3] = fmaf(a.z, bb.w, acc[2][3]);
            acc[3][0] = fmaf(a.w, bb.x, acc[3][0]);
            acc[3][1] = fmaf(a.w, bb.y, acc[3][1]);
            acc[3][2] = fmaf(a.w, bb.z, acc[3][2]);
            acc[3][3] = fmaf(a.w, bb.w, acc[3][3]);
        }

        // phase B: g-weighted stats over the full 256-px chunk
        if (w < 5) {
            #pragma unroll 4
            for (int x = 0; x < 256; ++x)
                accg = fmaf(gs[x][w], zs[x][l], accg);
        } else if (w == 5) {
            #pragma unroll 4
            for (int x = 0; x < 256; ++x) accs += zs[x][l];
        } else if (w == 6 && l < 5) {
            #pragma unroll 4
            for (int x = 0; x < 256; ++x) accgs += gs[x][l];
        }
    }

    float* p = g_part1 + (size_t)(b * TILES_ + tile) * SST_;
    // ZZ: 4 team slices (reduced in k_prep)
    #pragma unroll
    for (int u = 0; u < 4; ++u)
        #pragma unroll
        for (int v = 0; v < 4; ++v)
            p[ZZOFF_ + team * 1024 + (4 * ti + u) * 32 + (4 * tj + v)] = acc[u][v];
    if (w < 5)           p[GZOFF_ + w * 32 + l] = accg;
    if (w == 5)          p[SOFF_ + l] = accs;
    if (w == 6 && l < 5) p[GSOFF_ + l] = accgs;
}

__device__ __forceinline__ float wsum(float v)
{
    #pragma unroll
    for (int o = 16; o; o >>= 1) v += __shfl_xor_sync(0xffffffffu, v, o);
    return v;
}

// =====================================================================
// Kernel 2: per-(b,k) block: reduce tile partials (256 threads), then
// warp 0 does mu, cov, Cholesky, P = L^-T L^-1, q, r, logdet.
// =====================================================================
__global__ __launch_bounds__(256) void k_prep()
{
    const int bk = blockIdx.x;
    const int b = bk / K_, k = bk % K_;
    const int tid = threadIdx.x, l = tid & 31;
    __shared__ float st[1222];          // ZZ(1024) GZ_k(32) S(32) Gs(1) layout below
    __shared__ float A [32][33];
    __shared__ float Ai[32][33];
    __shared__ float Pm[32][33];
    __shared__ float mu[32], Sv[32];

    const float* p1 = g_part1 + (size_t)b * TILES_ * SST_;

    // ZZ: sum 32 tiles x 4 team slices
    for (int s = tid; s < 1024; s += 256) {
        float acc = 0.f;
        for (int t = 0; t < TILES_; ++t) {
            const float* pp = p1 + (size_t)t * SST_;
            acc += pp[s] + pp[1024 + s] + pp[2048 + s] + pp[3072 + s];
        }
        st[s] = acc;
    }
    // GZ row k, S, Gs_k
    if (tid < 32) {
        float a1 = 0.f, a2 = 0.f, a3 = 0.f;
        for (int t = 0; t < TILES_; ++t) {
            const float* pp = p1 + (size_t)t * SST_;
            a1 += pp[GZOFF_ + k * 32 + tid];
            a2 += pp[SOFF_ + tid];
            if (tid == 0) a3 += pp[GSOFF_ + k];
        }
        st[1024 + tid] = a1;
        st[1056 + tid] = a2;
        if (tid == 0) st[1088] = a3;
    }
    __syncthreads();
    if (tid >= 32) return;

    const float Gs = st[1088];

    // mu = GZ/(Gs+eps), then L2-normalize over channels
    float m = st[1024 + l] / (Gs + EPS_);
    float nrm = sqrtf(wsum(m * m));
    m = m / (EPS_ + nrm);
    mu[l] = m; Sv[l] = st[1056 + l];
    __syncwarp();

    // cov = ZZ - mu S^T - S mu^T + hw mu mu^T
    #pragma unroll 1
    for (int i = 0; i < 32; ++i)
        A[i][l] = st[i * 32 + l] - mu[i] * Sv[l] - m * Sv[i] + 65536.0f * mu[i] * m;
    __syncwarp();

    // diag += max(diag, eps)
    {
        float dg = A[l][l];
        A[l][l] = dg + fmaxf(dg, EPS_);
    }
    __syncwarp();

    // Frobenius normalize
    float sq = 0.f;
    for (int i = 0; i < 32; ++i) sq += A[i][l] * A[i][l];
    float fro = sqrtf(wsum(sq));
    float sc = 1.0f / (EPS_ + fro);
    for (int i = 0; i < 32; ++i) A[i][l] *= sc;
    __syncwarp();

    // Cholesky (lower, in place)
    for (int j = 0; j < 32; ++j) {
        if (l == 0) A[j][j] = sqrtf(A[j][j]);
        __syncwarp();
        float inv = 1.0f / A[j][j];
        if (l > j) A[l][j] *= inv;
        __syncwarp();
        for (int m2 = j + 1; m2 < 32; ++m2) {
            float lmj = A[m2][j];
            if (l >= m2) A[l][m2] = fmaf(-A[l][j], lmj, A[l][m2]);
        }
        __syncwarp();
    }
    float logdet2 = 2.0f * wsum(logf(A[l][l]));

    // Ai = L^-1 (lower); lane l owns column l
    for (int i = 0; i < 32; ++i) Ai[i][l] = 0.0f;
    __syncwarp();
    Ai[l][l] = 1.0f / A[l][l];
    for (int i = l + 1; i < 32; ++i) {
        float s = 0.f;
        for (int m2 = l; m2 < i; ++m2) s = fmaf(A[i][m2], Ai[m2][l], s);
        Ai[i][l] = -s / A[i][i];
    }
    __syncwarp();

    // P = Ai^T Ai
    for (int i = 0; i < 32; ++i) {
        float s = 0.f;
        for (int m2 = 0; m2 < 32; ++m2) s = fmaf(Ai[m2][i], Ai[m2][l], s);
        Pm[i][l] = s;
    }
    __syncwarp();

    // q = P mu, r = mu^T P mu
    float q = 0.f;
    for (int j = 0; j < 32; ++j) q = fmaf(Pm[l][j], mu[j], q);
    float r = wsum(mu[l] * q);

    // pack: upper triangle, halved diagonal, zero below
    float* Pd = g_P + (size_t)bk * (C_ * C_);
    for (int i = 0; i < 32; ++i) {
        float v = (l < i) ? 0.0f : ((l == i) ? 0.5f * Pm[i][i] : Pm[i][l]);
        Pd[i * 32 + l] = v;
    }
    g_Hb[bk * C_ + l] = -q;
    if (l == 0) {
        float phi = Gs / 65536.0f;
        g_Ck[bk] = phi - 0.5f * (CLOG2PI_ + logdet2 + r);
    }
}

// =====================================================================
// Kernel 3: per-pixel quadratic form for ALL 5 components; each thread
// handles 2 pixels so every P load (LDS.128) is amortized over both.
// Grid (CHUNKS_, B_), 256 threads, 2 pixels per thread.
// v_n = -( z^T P z /2 - q.z )  (r folded into the constant)
// =====================================================================
__global__ __launch_bounds__(256, 2) void k_maha(const float* __restrict__ z)
{
    const int chunk = blockIdx.x;
    const int b     = blockIdx.y;
    const int tid   = threadIdx.x;
    const int wid   = tid >> 5, lid = tid & 31;

    __shared__ __align__(16) float Ps[K_ * 1024];   // 20KB: 5 packed P
    __shared__ float Hs[K_ * 32];
    __shared__ float rmx[8 * K_], rsm[8 * K_];

    const float4* Pb4 = reinterpret_cast<const float4*>(g_P + (size_t)b * K_ * 1024);
    float4* Ps4 = reinterpret_cast<float4*>(Ps);
    #pragma unroll
    for (int r = 0; r < K_; ++r) Ps4[tid + r * 256] = Pb4[tid + r * 256];
    if (tid < K_ * 32) Hs[tid] = g_Hb[b * K_ * 32 + tid];
    __syncthreads();

    const float* zb = z + (size_t)b * C_ * HW_;
    const int n2 = chunk * 512 + tid * 2;

    float zr0[32], zr1[32];
    #pragma unroll
    for (int c = 0; c < 32; ++c) {
        const float2 v = *reinterpret_cast<const float2*>(zb + (size_t)c * HW_ + n2);
        zr0[c] = v.x; zr1[c] = v.y;
    }

    float mxk[K_], smk[K_];

    #pragma unroll 1
    for (int k = 0; k < K_; ++k) {
        const float* Pk = &Ps[k * 1024];
        const float* Hk = &Hs[k * 32];
        float s0 = 0.0f, s1 = 0.0f;
        #pragma unroll
        for (int c = 0; c < 32; ++c) {
            float t0 = Hk[c], t1 = Hk[c];
            #pragma unroll
            for (int j = (c & ~3); j < 32; j += 4) {
                const float4 pv = *reinterpret_cast<const float4*>(&Pk[c * 32 + j]);
                t0 = fmaf(pv.x, zr0[j + 0], t0);
                t1 = fmaf(pv.x, zr1[j + 0], t1);
                t0 = fmaf(pv.y, zr0[j + 1], t0);
                t1 = fmaf(pv.y, zr1[j + 1], t1);
                t0 = fmaf(pv.z, zr0[j + 2], t0);
                t1 = fmaf(pv.z, zr1[j + 2], t1);
                t0 = fmaf(pv.w, zr0[j + 3], t0);
                t1 = fmaf(pv.w, zr1[j + 3], t1);
            }
            s0 = fmaf(zr0[c], t0, s0);
            s1 = fmaf(zr1[c], t1, s1);
        }
        const float v0 = -s0, v1 = -s1;
        const float m = fmaxf(v0, v1);
        mxk[k] = m;
        smk[k] = __expf(v0 - m) + __expf(v1 - m);
    }

    // warp reduce (logsumexp-merge), then cross-warp via smem
    #pragma unroll
    for (int k = 0; k < K_; ++k) {
        float m = mxk[k], s = smk[k];
        #pragma unroll
        for (int o = 16; o; o >>= 1) {
            float m2 = __shfl_xor_sync(0xffffffffu, m, o);
            float s2 = __shfl_xor_sync(0xffffffffu, s, o);
            float nm = fmaxf(m, m2);
            s = s * __expf(m - nm) + s2 * __expf(m2 - nm);
            m = nm;
        }
        if (lid == 0) { rmx[wid * K_ + k] = m; rsm[wid * K_ + k] = s; }
    }
    __syncthreads();
    if (tid < K_) {
        float m = rmx[tid], s = rsm[tid];
        #pragma unroll
        for (int w2 = 1; w2 < 8; ++w2) {
            float m2 = rmx[w2 * K_ + tid], s2 = rsm[w2 * K_ + tid];
            float nm = fmaxf(m, m2);
            s = s * __expf(m - nm) + s2 * __expf(m2 - nm);
            m = nm;
        }
        float* o = g_part2 + (size_t)((b * K_ + tid) * CHUNKS_ + chunk) * 2;
        o[0] = m; o[1] = s;
    }
}

// =====================================================================
// Kernel 4: combine chunk partials -> energy scalar
// =====================================================================
__global__ void k_final(float* __restrict__ out)
{
    __shared__ float acc[64];
    const int t = threadIdx.x;
    float val = 0.0f;
    if (t < B_ * K_) {
        float m = -CUDART_INF_F, s = 0.0f;
        for (int c = 0; c < CHUNKS_; ++c) {
            const float* o = g_part2 + (size_t)(t * CHUNKS_ + c) * 2;
            float m2 = o[0], s2 = o[1];
            float nm = fmaxf(m, m2);
            s = s * __expf(m - nm) + s2 * __expf(m2 - nm);
            m = nm;
        }
        val = g_Ck[t] + m + logf(s);
    }
    acc[t] = val;
    __syncthreads();
    for (int off = 32; off; off >>= 1) {
        if (t < off) acc[t] += acc[t + off];
        __syncthreads();
    }
    if (t == 0) out[0] = -(acc[0] / 40.0f) / 65536.0f;
}

// =====================================================================
extern "C" void kernel_launch(void* const* d_in, const int* in_sizes, int n_in,
                              void* d_out, int out_size)
{
    (void)in_sizes; (void)n_in; (void)out_size;
    const float* z = (const float*)d_in[0];
    const float* g = (const float*)d_in[1];

    k_stats <<<dim3(TILES_, B_), 256>>>(z, g);
    k_prep  <<<B_ * K_, 256>>>();
    k_maha  <<<dim3(CHUNKS_, B_), 256>>>(z);
    k_final <<<1, 64>>>((float*)d_out);
}